// round 12
// baseline (speedup 1.0000x reference)
#include <cuda_runtime.h>
#include <math.h>

#define B 96
#define D 512
#define RPB 4                 // rows of the dist matrix per block
#define GX (B / RPB)          // 24
#define GY 3                  // 32 columns per block-y
#define NBLK (GX * GY)        // 72 blocks
#define SDP 97                // padded row stride for shared dist (bank-conflict-free columns)

// ---------------- device scratch (no allocations allowed) ----------------
__device__ float        g_dist[B * B];
__device__ unsigned int g_count = 0;

__global__ __launch_bounds__(1024, 1)
void k_fused(const float* __restrict__ embs, const int* __restrict__ raw_idtys,
             float* __restrict__ out) {
    __shared__ float4   srow[RPB * (D / 4)];   // 8 KB: staged A-rows
    __shared__ float    s_ni[RPB];             // norms of staged rows
    __shared__ float    sd[B * SDP];           // 36.4 KB: full dist matrix (epilogue)
    __shared__ int      sy[B];
    __shared__ float    s_trip[B], s_ipart[B];
    __shared__ int      s_pos[B], s_neg[B];
    __shared__ int      s_bad;
    __shared__ unsigned s_ticket;

    const int tid  = threadIdx.x;
    const int w    = tid >> 5;
    const int lane = tid & 31;
    const int i0   = blockIdx.x * RPB;

    // ---- stage RPB embedding rows ----
    if (tid < RPB * (D / 4)) {
        int r = tid >> 7, c = tid & 127;
        srow[tid] = ((const float4*)(embs + (size_t)(i0 + r) * D))[c];
    }
    __syncthreads();

    // ---- norms of staged rows (warps 0..RPB-1) ----
    if (w < RPB) {
        float acc = 0.0f;
#pragma unroll
        for (int c = 0; c < 4; c++) {
            float4 a = srow[w * 128 + lane + 32 * c];
            acc += a.x * a.x + a.y * a.y + a.z * a.z + a.w * a.w;
        }
#pragma unroll
        for (int o = 16; o; o >>= 1) acc += __shfl_xor_sync(0xffffffffu, acc, o);
        if (lane == 0) s_ni[w] = acc;
    }
    __syncthreads();

    // ---- dot products: warp w owns column j, 4 rows each ----
    {
        const int j = blockIdx.y * 32 + w;
        const float4* rj = (const float4*)(embs + (size_t)j * D);
        float s0 = 0.f, s1 = 0.f, s2 = 0.f, s3 = 0.f, nj = 0.f;
#pragma unroll
        for (int c = 0; c < 4; c++) {
            float4 b  = rj[lane + 32 * c];
            nj += b.x * b.x + b.y * b.y + b.z * b.z + b.w * b.w;
            float4 a0 = srow[  0 + lane + 32 * c];
            float4 a1 = srow[128 + lane + 32 * c];
            float4 a2 = srow[256 + lane + 32 * c];
            float4 a3 = srow[384 + lane + 32 * c];
            s0 += a0.x * b.x + a0.y * b.y + a0.z * b.z + a0.w * b.w;
            s1 += a1.x * b.x + a1.y * b.y + a1.z * b.z + a1.w * b.w;
            s2 += a2.x * b.x + a2.y * b.y + a2.z * b.z + a2.w * b.w;
            s3 += a3.x * b.x + a3.y * b.y + a3.z * b.z + a3.w * b.w;
        }
#pragma unroll
        for (int o = 16; o; o >>= 1) {
            s0 += __shfl_xor_sync(0xffffffffu, s0, o);
            s1 += __shfl_xor_sync(0xffffffffu, s1, o);
            s2 += __shfl_xor_sync(0xffffffffu, s2, o);
            s3 += __shfl_xor_sync(0xffffffffu, s3, o);
            nj += __shfl_xor_sync(0xffffffffu, nj, o);
        }
        if (lane < RPB) {
            float s = (lane == 0) ? s0 : (lane == 1) ? s1 : (lane == 2) ? s2 : s3;
            int   i = i0 + lane;
            float v = fmaxf(s_ni[lane] + nj - 2.0f * s, 0.0f);   // ref: sq_j - 2 dot + sq_i, clamped
            float dres = (i == j || v <= 0.0f) ? 0.0f : sqrtf(v); // ref zero-handling
            g_dist[i * B + j] = dres;
        }
    }

    // ---- grid sync: last-arriving block runs the epilogue ----
    __threadfence();                 // every thread releases its dist writes to gpu scope
    __syncthreads();
    if (tid == 0) s_ticket = atomicAdd(&g_count, 1u);
    __syncthreads();
    if (s_ticket != NBLK - 1) return;
    if (tid == 0) g_count = 0;       // reset for next graph replay (all others finished)
    __threadfence();                 // acquire side before reading peer blocks' writes

    // ================= EPILOGUE (last block only, 1024 threads) =================

    // identity decode: int64-LE vs int32 autodetect
    if (tid == 0) s_bad = 0;
    __syncthreads();
    if (tid < 48) {
        int lo = raw_idtys[2 * tid];
        int hi = raw_idtys[2 * tid + 1];
        if (hi != 0 || (unsigned)lo >= 16u) s_bad = 1;   // benign race, same value
    }
    __syncthreads();
    if (tid < B) sy[tid] = s_bad ? raw_idtys[tid] : raw_idtys[2 * tid];

    // stage the full dist matrix into padded shared (L1-bypassing loads)
    for (int idx = tid; idx < B * B; idx += 1024) {
        int i = idx / B, j = idx - i * B;
        sd[i * SDP + j] = __ldcg(g_dist + idx);
    }
    __syncthreads();

    // ---- batch-hard mining: warp w handles rows w, w+32, w+64 ----
#pragma unroll
    for (int rq = 0; rq < 3; rq++) {
        const int i  = w + 32 * rq;
        const int yi = sy[i];
        float dv[3]; int yv[3];
#pragma unroll
        for (int q = 0; q < 3; q++) {
            int j = lane + 32 * q;
            dv[q] = sd[i * SDP + j];
            yv[q] = sy[j];
        }
        // row max (unmasked) for the an_dist offset
        float maxd = fmaxf(fmaxf(dv[0], dv[1]), dv[2]);
#pragma unroll
        for (int o = 16; o; o >>= 1)
            maxd = fmaxf(maxd, __shfl_xor_sync(0xffffffffu, maxd, o));

        // hardest positive: argmax over mask_ap*d, first-occurrence ties
        float pbest = -1.0f; int pidx = 1 << 20;
#pragma unroll
        for (int q = 0; q < 3; q++) {
            int j = lane + 32 * q;
            float apv = (j != i && yv[q] == yi) ? dv[q] : 0.0f;
            if (apv > pbest) { pbest = apv; pidx = j; }
        }
#pragma unroll
        for (int o = 16; o; o >>= 1) {
            float ov = __shfl_xor_sync(0xffffffffu, pbest, o);
            int   oi = __shfl_xor_sync(0xffffffffu, pidx, o);
            if (ov > pbest || (ov == pbest && oi < pidx)) { pbest = ov; pidx = oi; }
        }

        // hardest negative: argmin over d + maxd*(1-mask_an), first-occurrence ties
        float nbest = 3.4e38f; int nidx = 1 << 20;
#pragma unroll
        for (int q = 0; q < 3; q++) {
            int j = lane + 32 * q;
            float anv = (yv[q] != yi) ? dv[q] : dv[q] + maxd;
            if (anv < nbest) { nbest = anv; nidx = j; }
        }
#pragma unroll
        for (int o = 16; o; o >>= 1) {
            float ov = __shfl_xor_sync(0xffffffffu, nbest, o);
            int   oi = __shfl_xor_sync(0xffffffffu, nidx, o);
            if (ov < nbest || (ov == nbest && oi < nidx)) { nbest = ov; nidx = oi; }
        }

        if (lane == 0) {
            s_trip[i] = fmaxf(pbest - nbest + 0.2f, 0.0f);
            s_pos[i]  = pidx;
            s_neg[i]  = nidx;
        }
    }
    __syncthreads();

    // ---- inter-class term (factorized): warp w handles a = w, w+32, w+64 ----
#pragma unroll
    for (int rq = 0; rq < 3; rq++) {
        const int a = w + 32 * rq;
        const int p = s_pos[a], n = s_neg[a];
        const int yp = sy[p],   yn = sy[n];

        float M = -1.0f;   // stays -1 iff no valid b
#pragma unroll
        for (int q = 0; q < 3; q++) {
            int b = lane + 32 * q;
            if (b != p && sy[b] == yp) M = fmaxf(M, sd[b * SDP + p]);  // stride-97: no conflicts
        }
#pragma unroll
        for (int o = 16; o; o >>= 1)
            M = fmaxf(M, __shfl_xor_sync(0xffffffffu, M, o));

        float s = 0.0f;
        if (M >= 0.0f && yp != yn) {
#pragma unroll
            for (int q = 0; q < 3; q++) {
                int l  = lane + 32 * q;
                int yl = sy[l];
                if (yl != yp && yl != yn)
                    s += fmaxf(M - sd[n * SDP + l] + 0.1f, 0.0f);
            }
        }
#pragma unroll
        for (int o = 16; o; o >>= 1) s += __shfl_xor_sync(0xffffffffu, s, o);
        if (lane == 0) s_ipart[a] = s;
    }
    __syncthreads();

    // ---- final reduce: mean(trip) + mean_{a,l}(inter), fixed deterministic order ----
    if (w == 0) {
        float acc = 0.0f;
#pragma unroll
        for (int q = 0; q < 3; q++) {
            int t = lane + 32 * q;
            acc += s_trip[t] * (1.0f / B) + s_ipart[t] * (1.0f / (96.0f * 96.0f));
        }
#pragma unroll
        for (int o = 16; o; o >>= 1) acc += __shfl_xor_sync(0xffffffffu, acc, o);
        if (lane == 0) out[0] = acc;
    }
}

// ---------------------------------------------------------------------------
extern "C" void kernel_launch(void* const* d_in, const int* in_sizes, int n_in,
                              void* d_out, int out_size) {
    (void)in_sizes; (void)n_in; (void)out_size;
    const float* embs = (const float*)d_in[0];
    const int*   idt  = (const int*)d_in[1];   // int32 view; layout autodetected
    float*       out  = (float*)d_out;

    k_fused<<<dim3(GX, GY), 1024>>>(embs, idt, out);
}

// round 13
// speedup vs baseline: 1.1210x; 1.1210x over previous
#include <cuda_runtime.h>
#include <math.h>

#define B 96
#define D 512
#define SDP 97   // padded row stride for shared dist (conflict-free column reads)

// ---------------- device scratch (no allocations allowed) ----------------
__device__ float g_dist[B * B];
__device__ float g_trip[B];
__device__ int   g_pos[B];
__device__ int   g_neg[B];

// ---------------------------------------------------------------------------
// Kernel 1: one block per row i. Computes dist row i (8 warps x 12 cols,
// diff-form, warp reduce), stores it to g_dist AND immediately does the
// batch-hard mining for row i in-block (no cross-block dependency).
// ---------------------------------------------------------------------------
__global__ __launch_bounds__(256, 4)
void k_dist_mine(const float* __restrict__ embs, const int* __restrict__ raw_idtys) {
    __shared__ float4 srow[D / 4];   // row i, 2 KB
    __shared__ float  drow[B];       // finished dist row
    __shared__ int    sy[B];
    __shared__ int    s_bad;

    const int i    = blockIdx.x;
    const int tid  = threadIdx.x;
    const int w    = tid >> 5;
    const int lane = tid & 31;

    if (tid < D / 4)
        srow[tid] = ((const float4*)(embs + (size_t)i * D))[tid];
    if (tid == 0) s_bad = 0;
    __syncthreads();

    // identity layout autodetect (int64-LE pairs look like (v<16, 0))
    if (tid < 48) {
        int lo = raw_idtys[2 * tid];
        int hi = raw_idtys[2 * tid + 1];
        if (hi != 0 || (unsigned)lo >= 16u) s_bad = 1;   // benign race, same value
    }

    // ---- distances: warp w computes cols j = w + 8*c, c = 0..11 ----
#pragma unroll
    for (int c = 0; c < 12; c++) {
        const int j = w + 8 * c;
        const float4* rj = (const float4*)(embs + (size_t)j * D);
        float s = 0.0f;
#pragma unroll
        for (int q = 0; q < 4; q++) {
            float4 a = srow[lane + 32 * q];
            float4 b = rj[lane + 32 * q];
            float d0 = a.x - b.x, d1 = a.y - b.y, d2 = a.z - b.z, d3 = a.w - b.w;
            s += d0 * d0 + d1 * d1 + d2 * d2 + d3 * d3;
        }
#pragma unroll
        for (int o = 16; o; o >>= 1) s += __shfl_xor_sync(0xffffffffu, s, o);
        if (lane == 0) {
            float dres = (i == j || s <= 0.0f) ? 0.0f : sqrtf(s);  // ref zero-handling
            drow[j] = dres;
            g_dist[i * B + j] = dres;
        }
    }
    __syncthreads();   // drow + s_bad ready

    if (tid < B) sy[tid] = s_bad ? raw_idtys[tid] : raw_idtys[2 * tid];
    __syncthreads();

    // ---- batch-hard mining for row i (warp 0 only, from smem) ----
    if (w == 0) {
        const int yi = sy[i];
        float dv[3]; int yv[3];
#pragma unroll
        for (int q = 0; q < 3; q++) {
            int j = lane + 32 * q;
            dv[q] = drow[j];
            yv[q] = sy[j];
        }
        // unmasked row max (for the an_dist offset)
        float maxd = fmaxf(fmaxf(dv[0], dv[1]), dv[2]);
#pragma unroll
        for (int o = 16; o; o >>= 1)
            maxd = fmaxf(maxd, __shfl_xor_sync(0xffffffffu, maxd, o));

        // hardest positive: argmax over mask_ap*d, first-occurrence ties
        float pbest = -1.0f; int pidx = 1 << 20;
#pragma unroll
        for (int q = 0; q < 3; q++) {
            int j = lane + 32 * q;
            float apv = (j != i && yv[q] == yi) ? dv[q] : 0.0f;
            if (apv > pbest) { pbest = apv; pidx = j; }   // strict > keeps smallest j per lane
        }
#pragma unroll
        for (int o = 16; o; o >>= 1) {
            float ov = __shfl_xor_sync(0xffffffffu, pbest, o);
            int   oi = __shfl_xor_sync(0xffffffffu, pidx, o);
            if (ov > pbest || (ov == pbest && oi < pidx)) { pbest = ov; pidx = oi; }
        }

        // hardest negative: argmin over d + maxd*(1-mask_an), first-occurrence ties
        float nbest = 3.4e38f; int nidx = 1 << 20;
#pragma unroll
        for (int q = 0; q < 3; q++) {
            int j = lane + 32 * q;
            float anv = (yv[q] != yi) ? dv[q] : dv[q] + maxd;
            if (anv < nbest) { nbest = anv; nidx = j; }
        }
#pragma unroll
        for (int o = 16; o; o >>= 1) {
            float ov = __shfl_xor_sync(0xffffffffu, nbest, o);
            int   oi = __shfl_xor_sync(0xffffffffu, nidx, o);
            if (ov < nbest || (ov == nbest && oi < nidx)) { nbest = ov; nidx = oi; }
        }

        if (lane == 0) {
            g_trip[i] = fmaxf(pbest - nbest + 0.2f, 0.0f);
            g_pos[i]  = pidx;
            g_neg[i]  = nidx;
        }
    }
}

// ---------------------------------------------------------------------------
// Kernel 2: inter-class term (factorized) + final mean. Single block, 1024 thr.
//   inter[a,l] = lmask(l) * relu(M_a - d[n_a,l] + 0.1)
//   M_a = max_{b != p_a, y_b == y_{p_a}} d[b, p_a]   (column read, stride-97)
// Final: mean(trip) + mean_{a,l}(inter), fixed deterministic order.
// ---------------------------------------------------------------------------
__global__ __launch_bounds__(1024, 1)
void k_epi(const int* __restrict__ raw_idtys, float* __restrict__ out) {
    __shared__ float sd[B * SDP];    // 36.4 KB padded dist matrix
    __shared__ int   sy[B];
    __shared__ float s_acc[B];       // per-a contribution
    __shared__ int   s_bad;

    const int tid  = threadIdx.x;
    const int w    = tid >> 5;
    const int lane = tid & 31;

    if (tid == 0) s_bad = 0;
    __syncthreads();
    if (tid < 48) {
        int lo = raw_idtys[2 * tid];
        int hi = raw_idtys[2 * tid + 1];
        if (hi != 0 || (unsigned)lo >= 16u) s_bad = 1;
    }

    // stage full dist matrix, padded
    for (int idx = tid; idx < B * B; idx += 1024) {
        int i = idx / B, j = idx - i * B;
        sd[i * SDP + j] = g_dist[idx];
    }
    __syncthreads();
    if (tid < B) sy[tid] = s_bad ? raw_idtys[tid] : raw_idtys[2 * tid];
    __syncthreads();

    // warp w handles a = w, w+32, w+64
#pragma unroll
    for (int rq = 0; rq < 3; rq++) {
        const int a = w + 32 * rq;
        const int p = g_pos[a], n = g_neg[a];
        const int yp = sy[p],   yn = sy[n];

        float M = -1.0f;   // stays -1 iff no valid b (empty positive set)
#pragma unroll
        for (int q = 0; q < 3; q++) {
            int b = lane + 32 * q;
            if (b != p && sy[b] == yp) M = fmaxf(M, sd[b * SDP + p]);  // conflict-free column
        }
#pragma unroll
        for (int o = 16; o; o >>= 1)
            M = fmaxf(M, __shfl_xor_sync(0xffffffffu, M, o));

        float s = 0.0f;
        if (M >= 0.0f && yp != yn) {
#pragma unroll
            for (int q = 0; q < 3; q++) {
                int l  = lane + 32 * q;
                int yl = sy[l];
                if (yl != yp && yl != yn)
                    s += fmaxf(M - sd[n * SDP + l] + 0.1f, 0.0f);
            }
        }
#pragma unroll
        for (int o = 16; o; o >>= 1) s += __shfl_xor_sync(0xffffffffu, s, o);

        if (lane == 0)
            s_acc[a] = g_trip[a] * (1.0f / B) + s * (1.0f / (96.0f * 96.0f));
    }
    __syncthreads();

    // final reduce over 96 values (warp 0, fixed order)
    if (w == 0) {
        float acc = 0.0f;
#pragma unroll
        for (int q = 0; q < 3; q++) acc += s_acc[lane + 32 * q];
#pragma unroll
        for (int o = 16; o; o >>= 1) acc += __shfl_xor_sync(0xffffffffu, acc, o);
        if (lane == 0) out[0] = acc;
    }
}

// ---------------------------------------------------------------------------
extern "C" void kernel_launch(void* const* d_in, const int* in_sizes, int n_in,
                              void* d_out, int out_size) {
    (void)in_sizes; (void)n_in; (void)out_size;
    const float* embs = (const float*)d_in[0];
    const int*   idt  = (const int*)d_in[1];   // int32 view; layout autodetected
    float*       out  = (float*)d_out;

    k_dist_mine<<<B, 256>>>(embs, idt);
    k_epi<<<1, 1024>>>(idt, out);
}

// round 14
// speedup vs baseline: 1.3102x; 1.1687x over previous
#include <cuda_runtime.h>
#include <math.h>

#define B 96
#define D 512

// ---------------- device scratch (no allocations allowed) ----------------
__device__ float              g_dist[B * B];
__device__ float              g_trip[B];
__device__ int                g_pos[B];
__device__ int                g_neg[B];
__device__ unsigned long long g_acc   = 0ull;   // fixed-point (2^38) loss accumulator
__device__ unsigned int       g_count = 0u;     // completion ticket

#define FP_SCALE     274877906944.0f            /* 2^38 */
#define FP_INV_SCALE (1.0 / 274877906944.0)

// ---------------------------------------------------------------------------
// Kernel 1: one block per row i, 32 warps. Warp w computes dist[i][j] for
// j = w, w+32, w+64 (4 independent accumulators -> chain depth 4, not 256),
// then warp 0 immediately does batch-hard mining for row i from smem.
// ---------------------------------------------------------------------------
__global__ __launch_bounds__(1024, 1)
void k_dist_mine(const float* __restrict__ embs, const int* __restrict__ raw) {
    __shared__ float4 srow[D / 4];   // row i, 2 KB
    __shared__ float  drow[B];
    __shared__ int    sy[B];
    __shared__ int    s_bad;

    const int i    = blockIdx.x;
    const int tid  = threadIdx.x;
    const int w    = tid >> 5;
    const int lane = tid & 31;

    if (tid < D / 4) srow[tid] = ((const float4*)(embs + (size_t)i * D))[tid];
    if (tid == 0)    s_bad = 0;
    __syncthreads();

    // identity layout autodetect (int64-LE pairs look like (v<16, 0))
    if (tid < 48) {
        int lo = raw[2 * tid], hi = raw[2 * tid + 1];
        if (hi != 0 || (unsigned)lo >= 16u) s_bad = 1;   // benign race, same value
    }

    // ---- distances: 3 columns per warp, short FMA chains ----
#pragma unroll
    for (int c = 0; c < 3; c++) {
        const int j = w + 32 * c;
        const float4* rj = (const float4*)(embs + (size_t)j * D);
        float s0 = 0.f, s1 = 0.f, s2 = 0.f, s3 = 0.f;
#pragma unroll
        for (int q = 0; q < 4; q++) {
            float4 a = srow[lane + 32 * q];
            float4 b = rj[lane + 32 * q];
            float d0 = a.x - b.x, d1 = a.y - b.y, d2 = a.z - b.z, d3 = a.w - b.w;
            s0 += d0 * d0; s1 += d1 * d1; s2 += d2 * d2; s3 += d3 * d3;
        }
        float s = (s0 + s1) + (s2 + s3);
#pragma unroll
        for (int o = 16; o; o >>= 1) s += __shfl_xor_sync(0xffffffffu, s, o);
        if (lane == 0) {
            float dres = (i == j || s <= 0.0f) ? 0.0f : sqrtf(s);  // ref zero-handling
            drow[j] = dres;
            g_dist[i * B + j] = dres;
        }
    }
    __syncthreads();                 // drow + s_bad ready
    if (tid < B) sy[tid] = s_bad ? raw[tid] : raw[2 * tid];
    __syncthreads();

    // ---- batch-hard mining for row i (warp 0, from smem) ----
    if (w == 0) {
        const int yi = sy[i];
        float dv[3]; int yv[3];
#pragma unroll
        for (int q = 0; q < 3; q++) {
            int j = lane + 32 * q;
            dv[q] = drow[j];
            yv[q] = sy[j];
        }
        // unmasked row max (for the an_dist offset)
        float maxd = fmaxf(fmaxf(dv[0], dv[1]), dv[2]);
#pragma unroll
        for (int o = 16; o; o >>= 1)
            maxd = fmaxf(maxd, __shfl_xor_sync(0xffffffffu, maxd, o));

        // hardest positive: argmax over mask_ap*d, first-occurrence ties
        float pbest = -1.0f; int pidx = 1 << 20;
#pragma unroll
        for (int q = 0; q < 3; q++) {
            int j = lane + 32 * q;
            float apv = (j != i && yv[q] == yi) ? dv[q] : 0.0f;
            if (apv > pbest) { pbest = apv; pidx = j; }   // strict > keeps smallest j per lane
        }
#pragma unroll
        for (int o = 16; o; o >>= 1) {
            float ov = __shfl_xor_sync(0xffffffffu, pbest, o);
            int   oi = __shfl_xor_sync(0xffffffffu, pidx, o);
            if (ov > pbest || (ov == pbest && oi < pidx)) { pbest = ov; pidx = oi; }
        }

        // hardest negative: argmin over d + maxd*(1-mask_an), first-occurrence ties
        float nbest = 3.4e38f; int nidx = 1 << 20;
#pragma unroll
        for (int q = 0; q < 3; q++) {
            int j = lane + 32 * q;
            float anv = (yv[q] != yi) ? dv[q] : dv[q] + maxd;
            if (anv < nbest) { nbest = anv; nidx = j; }
        }
#pragma unroll
        for (int o = 16; o; o >>= 1) {
            float ov = __shfl_xor_sync(0xffffffffu, nbest, o);
            int   oi = __shfl_xor_sync(0xffffffffu, nidx, o);
            if (ov < nbest || (ov == nbest && oi < nidx)) { nbest = ov; nidx = oi; }
        }

        if (lane == 0) {
            g_trip[i] = fmaxf(pbest - nbest + 0.2f, 0.0f);
            g_pos[i]  = pidx;
            g_neg[i]  = nidx;
        }
    }
}

// ---------------------------------------------------------------------------
// Kernel 2: factorized inter term + final mean, fully parallel (96 x 32).
//   inter[a,l] = lmask(l) * relu(M_a - d[n_a,l] + 0.1),
//   M_a = max_{b != p_a, y_b == y_{p_a}} d[b, p_a].
// Each block adds trip[a]/96 + sum_l inter[a,l]/9216 to an int64 fixed-point
// accumulator (associative -> deterministic). Last-arriving block writes out
// and resets scratch for the next graph replay.
// ---------------------------------------------------------------------------
__global__ __launch_bounds__(32, 32)
void k_inter(const int* __restrict__ raw, float* __restrict__ out) {
    const int a    = blockIdx.x;
    const int lane = threadIdx.x;

    // identity layout autodetect (48 pairs across 32 lanes)
    int bad;
    {
        int lo = raw[2 * lane], hi = raw[2 * lane + 1];
        int b  = (hi != 0) || ((unsigned)lo >= 16u);
        if (lane < 16) {
            int lo2 = raw[2 * (lane + 32)], hi2 = raw[2 * (lane + 32) + 1];
            b |= (hi2 != 0) || ((unsigned)lo2 >= 16u);
        }
        bad = __any_sync(0xffffffffu, b);
    }

    const int p  = g_pos[a], n = g_neg[a];
    const int yp = bad ? raw[p] : raw[2 * p];
    const int yn = bad ? raw[n] : raw[2 * n];

    int yv[3]; float dn[3];
#pragma unroll
    for (int q = 0; q < 3; q++) {
        int l = lane + 32 * q;
        yv[q] = bad ? raw[l] : raw[2 * l];
        dn[q] = g_dist[n * B + l];
    }

    float M = -1.0f;   // stays -1 iff no valid b (empty positive set)
#pragma unroll
    for (int q = 0; q < 3; q++) {
        int b = lane + 32 * q;
        if (b != p && yv[q] == yp) M = fmaxf(M, g_dist[b * B + p]);
    }
#pragma unroll
    for (int o = 16; o; o >>= 1)
        M = fmaxf(M, __shfl_xor_sync(0xffffffffu, M, o));

    float s = 0.0f;
    if (M >= 0.0f && yp != yn) {
#pragma unroll
        for (int q = 0; q < 3; q++)
            if (yv[q] != yp && yv[q] != yn)
                s += fmaxf(M - dn[q] + 0.1f, 0.0f);
    }
#pragma unroll
    for (int o = 16; o; o >>= 1) s += __shfl_xor_sync(0xffffffffu, s, o);

    if (lane == 0) {
        float c = g_trip[a] * (1.0f / 96.0f) + s * (1.0f / 9216.0f);   // c >= 0
        unsigned long long inc = (unsigned long long)__float2ll_rn(c * FP_SCALE);
        atomicAdd(&g_acc, inc);
        __threadfence();                          // my add visible before my ticket
        unsigned t = atomicAdd(&g_count, 1u);
        if (t == B - 1) {                         // all 96 adds are in
            unsigned long long tot = atomicAdd(&g_acc, 0ull);
            out[0] = (float)((double)tot * FP_INV_SCALE);
            g_acc   = 0ull;                       // reset for next graph replay
            g_count = 0u;
            __threadfence();
        }
    }
}

// ---------------------------------------------------------------------------
extern "C" void kernel_launch(void* const* d_in, const int* in_sizes, int n_in,
                              void* d_out, int out_size) {
    (void)in_sizes; (void)n_in; (void)out_size;
    const float* embs = (const float*)d_in[0];
    const int*   idt  = (const int*)d_in[1];   // int32 view; layout autodetected
    float*       out  = (float*)d_out;

    k_dist_mine<<<B, 1024>>>(embs, idt);
    k_inter<<<B, 32>>>(idt, out);
}